// round 11
// baseline (speedup 1.0000x reference)
#include <cuda_runtime.h>
#include <cuda_fp16.h>

// Problem constants (fixed shapes from reference)
#define BB 4
#define SS 4096
#define DD 1024
#define HD 128
#define BS (BB*SS)   // 16384 rows
#define RR 8         // scan lookahead block size
#define NBLK (SS/RR) // 512
#define CC 64        // chunk size for y reconstruction
#define NCH (SS/CC)

// ---------------------------------------------------------------------------
// Scratch (device globals; no allocation allowed in kernel_launch)
// ---------------------------------------------------------------------------
__device__ float g_q[BB*SS*HD];
__device__ float g_k[BB*SS*HD];
__device__ float g_v[BB*SS*HD];
__device__ float g_y[BB*SS*HD];
__device__ float g_e[BB*SS*HD];
__device__ float4 g_gram4[BB*SS*2];       // per (b,t): {G1..G4},{G5,G6,G7,0}
__device__ float g_wsnap[BB*NCH*HD*HD];   // W at chunk starts

// fp16-split operands: q-path ONLY (k/v feed the recurrence -> coherent split
// error is amplified ~linearly in S; q has no feedback and is safe)
__device__ __half g_xh[BS*DD], g_xl[BS*DD];
__device__ __half g_wqh[HD*DD], g_wql[HD*DD];   // Wq^T [HD][DD]

__device__ __forceinline__ float dot4(float4 a, float4 b) {
    return fmaf(a.x, b.x, fmaf(a.y, b.y, fmaf(a.z, b.z, a.w * b.w)));
}

// ---------------------------------------------------------------------------
// Split kernels: a = hi(fp16) + lo(fp16)
// ---------------------------------------------------------------------------
__global__ __launch_bounds__(256) void splitx_kernel(const float* __restrict__ x)
{
    const size_t i = (size_t)blockIdx.x * blockDim.x + threadIdx.x;  // float4 idx
    const float4 f = ((const float4*)x)[i];
    __half h0 = __float2half_rn(f.x), h1 = __float2half_rn(f.y);
    __half h2 = __float2half_rn(f.z), h3 = __float2half_rn(f.w);
    __half l0 = __float2half_rn(f.x - __half2float(h0));
    __half l1 = __float2half_rn(f.y - __half2float(h1));
    __half l2 = __float2half_rn(f.z - __half2float(h2));
    __half l3 = __float2half_rn(f.w - __half2float(h3));
    ((__half2*)g_xh)[2*i]     = __halves2half2(h0, h1);
    ((__half2*)g_xh)[2*i + 1] = __halves2half2(h2, h3);
    ((__half2*)g_xl)[2*i]     = __halves2half2(l0, l1);
    ((__half2*)g_xl)[2*i + 1] = __halves2half2(l2, l3);
}

__global__ __launch_bounds__(256) void splitwq_kernel(const float* __restrict__ Wq)
{
    const int r = blockIdx.x * blockDim.x + threadIdx.x;   // 0 .. DD*HD-1
    const int d = r >> 7, h = r & 127;
    const float f = Wq[r];
    __half hi = __float2half_rn(f);
    __half lo = __float2half_rn(f - __half2float(hi));
    g_wqh[h * DD + d] = hi;
    g_wql[h * DD + d] = lo;
}

// ---------------------------------------------------------------------------
// fp16-split tensor-core GEMM (3-term): q = x * Wq^T
// CTA tile 128x128, K-step 32, 8 warps (2x4), warp tile 64x32, m16n8k16.
// ---------------------------------------------------------------------------
__device__ __forceinline__ void mma16816(float* c, const unsigned* a, const unsigned* b)
{
    asm volatile(
        "mma.sync.aligned.m16n8k16.row.col.f32.f16.f16.f32 "
        "{%0,%1,%2,%3},{%4,%5,%6,%7},{%8,%9},{%0,%1,%2,%3};"
        : "+f"(c[0]), "+f"(c[1]), "+f"(c[2]), "+f"(c[3])
        : "r"(a[0]), "r"(a[1]), "r"(a[2]), "r"(a[3]), "r"(b[0]), "r"(b[1]));
}

__global__ __launch_bounds__(256) void qmma_kernel()
{
    __shared__ unsigned AsH[128*20], AsL[128*20], BsH[128*20], BsL[128*20];

    const int bm = blockIdx.x;
    const int N = HD, K = DD;

    const int t = threadIdx.x;
    const int lane = t & 31, wid = t >> 5;
    const int g = lane >> 2, tg = lane & 3;
    const int warpM = wid >> 2, warpN = wid & 3;

    const int lr = t >> 1, lc = t & 1;
    const __half* aPh = g_xh + (size_t)(bm * 128 + lr) * K + lc * 16;
    const __half* aPl = g_xl + (size_t)(bm * 128 + lr) * K + lc * 16;
    const __half* bPh = g_wqh + (size_t)lr * K + lc * 16;
    const __half* bPl = g_wql + (size_t)lr * K + lc * 16;
    const int sts = lr * 20 + lc * 8;

    float c[4][4][4];
#pragma unroll
    for (int mt = 0; mt < 4; mt++)
#pragma unroll
        for (int nt = 0; nt < 4; nt++)
#pragma unroll
            for (int j = 0; j < 4; j++) c[mt][nt][j] = 0.f;

    int4 ra0  = *(const int4*)aPh;       int4 ra1  = *(const int4*)(aPh + 8);
    int4 ral0 = *(const int4*)aPl;       int4 ral1 = *(const int4*)(aPl + 8);
    int4 rb0  = *(const int4*)bPh;       int4 rb1  = *(const int4*)(bPh + 8);
    int4 rbl0 = *(const int4*)bPl;       int4 rbl1 = *(const int4*)(bPl + 8);
    *(int4*)&AsH[sts] = ra0;   *(int4*)&AsH[sts + 4] = ra1;
    *(int4*)&AsL[sts] = ral0;  *(int4*)&AsL[sts + 4] = ral1;
    *(int4*)&BsH[sts] = rb0;   *(int4*)&BsH[sts + 4] = rb1;
    *(int4*)&BsL[sts] = rbl0;  *(int4*)&BsL[sts + 4] = rbl1;
    __syncthreads();

    const int KT = K / 32;
    for (int kt = 0; kt < KT; kt++) {
        if (kt + 1 < KT) {
            const int o = (kt + 1) * 32;
            ra0  = *(const int4*)(aPh + o);      ra1  = *(const int4*)(aPh + o + 8);
            ral0 = *(const int4*)(aPl + o);      ral1 = *(const int4*)(aPl + o + 8);
            rb0  = *(const int4*)(bPh + o);      rb1  = *(const int4*)(bPh + o + 8);
            rbl0 = *(const int4*)(bPl + o);      rbl1 = *(const int4*)(bPl + o + 8);
        }
#pragma unroll
        for (int s = 0; s < 2; s++) {
            unsigned aH[4][4], aL[4][4], bH[4][2], bL[4][2];
#pragma unroll
            for (int mt = 0; mt < 4; mt++) {
                const int r0 = (warpM * 64 + mt * 16 + g) * 20 + s * 8 + tg;
                aH[mt][0] = AsH[r0];       aH[mt][1] = AsH[r0 + 160];
                aH[mt][2] = AsH[r0 + 4];   aH[mt][3] = AsH[r0 + 164];
                aL[mt][0] = AsL[r0];       aL[mt][1] = AsL[r0 + 160];
                aL[mt][2] = AsL[r0 + 4];   aL[mt][3] = AsL[r0 + 164];
            }
#pragma unroll
            for (int nt = 0; nt < 4; nt++) {
                const int n0 = (warpN * 32 + nt * 8 + g) * 20 + s * 8 + tg;
                bH[nt][0] = BsH[n0];  bH[nt][1] = BsH[n0 + 4];
                bL[nt][0] = BsL[n0];  bL[nt][1] = BsL[n0 + 4];
            }
#pragma unroll
            for (int mt = 0; mt < 4; mt++)
#pragma unroll
                for (int nt = 0; nt < 4; nt++) {
                    mma16816(c[mt][nt], aH[mt], bH[nt]);
                    mma16816(c[mt][nt], aH[mt], bL[nt]);
                    mma16816(c[mt][nt], aL[mt], bH[nt]);
                }
        }
        __syncthreads();
        if (kt + 1 < KT) {
            *(int4*)&AsH[sts] = ra0;   *(int4*)&AsH[sts + 4] = ra1;
            *(int4*)&AsL[sts] = ral0;  *(int4*)&AsL[sts + 4] = ral1;
            *(int4*)&BsH[sts] = rb0;   *(int4*)&BsH[sts + 4] = rb1;
            *(int4*)&BsL[sts] = rbl0;  *(int4*)&BsL[sts + 4] = rbl1;
            __syncthreads();
        }
    }

#pragma unroll
    for (int mt = 0; mt < 4; mt++)
#pragma unroll
        for (int nt = 0; nt < 4; nt++) {
            const int row = bm * 128 + warpM * 64 + mt * 16 + g;
            const int col = warpN * 32 + nt * 8 + 2 * tg;
            *(float2*)&g_q[(size_t)row * N + col]       = make_float2(c[mt][nt][0], c[mt][nt][1]);
            *(float2*)&g_q[(size_t)(row + 8) * N + col] = make_float2(c[mt][nt][2], c[mt][nt][3]);
        }
}

// ---------------------------------------------------------------------------
// fp32 SGEMM body, double-buffered smem (one __syncthreads per K-step)
// ---------------------------------------------------------------------------
__device__ __forceinline__ void sgemm_body(
    const float* __restrict__ A, const float* __restrict__ Bm,
    float* __restrict__ C, int M, int N, int K, int bx, int by)
{
    __shared__ float As[2][8][128];
    __shared__ float Bs[2][8][132];

    const int tid = threadIdx.x;
    const int ty = tid >> 4;
    const int tx = tid & 15;
    const int a_r = tid >> 1;
    const int a_c = (tid & 1) << 2;
    const int b_r = tid >> 5;
    const int b_c = (tid & 31) << 2;

    const float* Ab = A + (size_t)by * 128 * K;
    const float* Bb = Bm + bx * 128;

    float acc[8][8];
#pragma unroll
    for (int i = 0; i < 8; i++)
#pragma unroll
        for (int j = 0; j < 8; j++) acc[i][j] = 0.f;

    // preload tile 0
    float4 av = *(const float4*)(Ab + (size_t)a_r * K + a_c);
    float4 bv = *(const float4*)(Bb + (size_t)b_r * N + b_c);
    As[0][a_c + 0][a_r] = av.x;
    As[0][a_c + 1][a_r] = av.y;
    As[0][a_c + 2][a_r] = av.z;
    As[0][a_c + 3][a_r] = av.w;
    *(float4*)&Bs[0][b_r][b_c] = bv;
    __syncthreads();

    int buf = 0;
    for (int k0 = 0; k0 < K; k0 += 8) {
        const bool more = (k0 + 8 < K);
        if (more) {
            av = *(const float4*)(Ab + (size_t)a_r * K + k0 + 8 + a_c);
            bv = *(const float4*)(Bb + (size_t)(k0 + 8 + b_r) * N + b_c);
        }
#pragma unroll
        for (int kk = 0; kk < 8; kk++) {
            float a[8], b[8];
#pragma unroll
            for (int i = 0; i < 8; i++) a[i] = As[buf][kk][ty * 8 + i];
#pragma unroll
            for (int j = 0; j < 8; j++) b[j] = Bs[buf][kk][tx * 8 + j];
#pragma unroll
            for (int i = 0; i < 8; i++)
#pragma unroll
                for (int j = 0; j < 8; j++) acc[i][j] = fmaf(a[i], b[j], acc[i][j]);
        }
        if (more) {
            As[buf ^ 1][a_c + 0][a_r] = av.x;
            As[buf ^ 1][a_c + 1][a_r] = av.y;
            As[buf ^ 1][a_c + 2][a_r] = av.z;
            As[buf ^ 1][a_c + 3][a_r] = av.w;
            *(float4*)&Bs[buf ^ 1][b_r][b_c] = bv;
            __syncthreads();
            buf ^= 1;
        }
    }

    float* Cb = C + (size_t)(by * 128 + ty * 8) * N + bx * 128 + tx * 8;
#pragma unroll
    for (int i = 0; i < 8; i++) {
        *(float4*)(Cb + (size_t)i * N)     = make_float4(acc[i][0], acc[i][1], acc[i][2], acc[i][3]);
        *(float4*)(Cb + (size_t)i * N + 4) = make_float4(acc[i][4], acc[i][5], acc[i][6], acc[i][7]);
    }
}

// Fused K,V projections in fp32 (recurrence-sensitive operands)
__global__ __launch_bounds__(256) void kvgemm_kernel(
    const float* __restrict__ x, const float* __restrict__ Wk,
    const float* __restrict__ Wv)
{
    const float* Bm = (blockIdx.z == 0) ? Wk : Wv;
    float* C = (blockIdx.z == 0) ? g_k : g_v;
    sgemm_body(x, Bm, C, BS, HD, DD, 0, blockIdx.y);
}

__global__ __launch_bounds__(256) void outgemm_kernel(
    const float* __restrict__ Wo, float* __restrict__ out)
{
    sgemm_body(g_y, Wo, out, BS, DD, HD, blockIdx.x, blockIdx.y);
}

// ---------------------------------------------------------------------------
// Gram kernel: one warp per (b,t): G_d[t] = k_{t-d}.k_t for d=1..7
// ---------------------------------------------------------------------------
__global__ __launch_bounds__(256) void gram_kernel()
{
    const int w = (blockIdx.x * blockDim.x + threadIdx.x) >> 5;  // b*SS + t
    const int lane = threadIdx.x & 31;
    if (w >= BB * SS) return;
    const int t = w & (SS - 1);

    float4 kc = *(const float4*)(g_k + (size_t)w * HD + lane * 4);
    float dd[7];
#pragma unroll
    for (int d2 = 1; d2 <= 7; d2++) {
        float4 kd = make_float4(0.f, 0.f, 0.f, 0.f);
        if (t >= d2) kd = *(const float4*)(g_k + (size_t)(w - d2) * HD + lane * 4);
        dd[d2 - 1] = dot4(kd, kc);
    }
#pragma unroll
    for (int s = 16; s; s >>= 1) {
#pragma unroll
        for (int j = 0; j < 7; j++) dd[j] += __shfl_xor_sync(~0u, dd[j], s);
    }
    if (lane == 0) {
        g_gram4[(size_t)w * 2]     = make_float4(dd[0], dd[1], dd[2], dd[3]);
        g_gram4[(size_t)w * 2 + 1] = make_float4(dd[4], dd[5], dd[6], 0.f);
    }
}

// ---------------------------------------------------------------------------
// Blocked-lookahead error scan, R=8. k via 4-stage cp.async smem pipeline;
// pipelined 5-stage shuffle reduction over 8 independent values.
// ---------------------------------------------------------------------------
__device__ __forceinline__ void cp_async16(unsigned smem_addr, const void* gptr)
{
    asm volatile("cp.async.cg.shared.global [%0], [%1], 16;"
                 :: "r"(smem_addr), "l"(gptr));
}
__device__ __forceinline__ void cp_commit() {
    asm volatile("cp.async.commit_group;");
}
__device__ __forceinline__ void cp_wait2() {
    asm volatile("cp.async.wait_group 2;");
}

__global__ __launch_bounds__(64) void scan_kernel(
    const float* __restrict__ lr, const float* __restrict__ state,
    float* __restrict__ wfinal)
{
    __shared__ float  ksm[2][4][RR][HD];   // [warp][stage][row][float] = 32KB
    __shared__ float4 gwbuf[2][2][16];     // gram double buffer per warp

    const int warp = (blockIdx.x * blockDim.x + threadIdx.x) >> 5;  // 0..511
    const int wl = (threadIdx.x >> 5);
    const int lane = threadIdx.x & 31;
    const int b = warp >> 7;
    const int i = warp & 127;
    const float eta = __ldg(lr);

    const float* kp = g_k + (size_t)b * SS * HD;
    const float* vp = g_v + (size_t)b * SS * HD + i;
    const float4* gp4 = g_gram4 + (size_t)b * SS * 2;
    float* ep = g_e + (size_t)b * SS * HD + i;

    float4 Wr = *(const float4*)(state + (size_t)(b * HD + i) * HD + lane * 4);

    unsigned kbase = (unsigned)__cvta_generic_to_shared(&ksm[wl][0][0][lane * 4]);

    float vc[RR], vn1[RR], vn2[RR];
#pragma unroll
    for (int r = 0; r < RR; r++)
        cp_async16(kbase + (0 * RR + r) * (HD * 4), kp + (size_t)r * HD + lane * 4);
    cp_commit();
#pragma unroll
    for (int r = 0; r < RR; r++)
        cp_async16(kbase + (1 * RR + r) * (HD * 4), kp + (size_t)(RR + r) * HD + lane * 4);
    cp_commit();
#pragma unroll
    for (int r = 0; r < RR; r++) {
        vc[r]  = vp[(size_t)r * HD];
        vn1[r] = vp[(size_t)(RR + r) * HD];
    }
    if (lane < 16) gwbuf[wl][0][lane] = gp4[lane];
    __syncwarp();

    for (int blk = 0; blk < NBLK; blk++) {
        const int T = blk * RR;
        const int cur = blk & 1;
        const int stage = blk & 3;

        if ((blk & 7) == 0) {
            const int c = blk >> 3;
            *(float4*)(g_wsnap + ((size_t)((b * NCH + c) * HD + i)) * HD + lane * 4) = Wr;
        }

        // prefetch k for blk+2 into stage (blk+2)&3
        const int T2 = ((blk + 2 < NBLK) ? (blk + 2) : (NBLK - 1)) * RR;
        const int st2 = (blk + 2) & 3;
#pragma unroll
        for (int r = 0; r < RR; r++)
            cp_async16(kbase + (st2 * RR + r) * (HD * 4), kp + (size_t)(T2 + r) * HD + lane * 4);
        cp_commit();

        // v prefetch depth 2 (registers)
#pragma unroll
        for (int r = 0; r < RR; r++) vn2[r] = vp[(size_t)(T2 + r) * HD];

        // gram prefetch depth 1
        const int T1 = ((blk + 1 < NBLK) ? (blk + 1) : (NBLK - 1)) * RR;
        float4 g4;
        if (lane < 16) g4 = gp4[(size_t)T1 * 2 + lane];

        cp_wait2();

        // 8 dots against fixed basis; pipelined 5-stage shuffle reduction
        float4 kcr[RR];
        float d[RR];
#pragma unroll
        for (int r = 0; r < RR; r++) {
            kcr[r] = *(const float4*)&ksm[wl][stage][r][lane * 4];
            d[r] = dot4(kcr[r], Wr);
        }
#pragma unroll
        for (int s = 16; s; s >>= 1) {
#pragma unroll
            for (int j = 0; j < RR; j++) d[j] += __shfl_xor_sync(~0u, d[j], s);
        }

        // publish next gram block
        if (lane < 16) gwbuf[wl][cur ^ 1][lane] = g4;
        __syncwarp();

        // serial scalar recurrence; Gram scalars read straight from smem
        const float* gbuf = (const float*)&gwbuf[wl][cur][0];
        float e[RR], ee[RR];
#pragma unroll
        for (int r = 0; r < RR; r++) {
            float acc = d[r] - vc[r];
#pragma unroll
            for (int dd2 = r; dd2 >= 1; --dd2)
                acc = fmaf(-ee[r - dd2], gbuf[r * 8 + dd2 - 1], acc);
            e[r] = acc;
            ee[r] = eta * acc;
        }

        if (lane == 0) {
#pragma unroll
            for (int r = 0; r < RR; r++) ep[(size_t)(T + r) * HD] = e[r];
        }

        // rank-8 update of basis
#pragma unroll
        for (int r = 0; r < RR; r++) {
            Wr.x = fmaf(-ee[r], kcr[r].x, Wr.x);
            Wr.y = fmaf(-ee[r], kcr[r].y, Wr.y);
            Wr.z = fmaf(-ee[r], kcr[r].z, Wr.z);
            Wr.w = fmaf(-ee[r], kcr[r].w, Wr.w);
        }

#pragma unroll
        for (int r = 0; r < RR; r++) { vc[r] = vn1[r]; vn1[r] = vn2[r]; }
    }

    *(float4*)(wfinal + (size_t)(b * HD + i) * HD + lane * 4) = Wr;
}

// ---------------------------------------------------------------------------
// ypass: per (chunk c, batch b) CTA reconstructs
//   Y = Q_c * W0^T - eta * tril_strict(Q_c K_c^T) * E_c   (fp32 output)
// ---------------------------------------------------------------------------
__global__ __launch_bounds__(256) void ypass_kernel(const float* __restrict__ lr)
{
    const int c = blockIdx.x, b = blockIdx.y;
    const size_t base = ((size_t)b * SS + (size_t)c * CC) * HD;
    const float* Q  = g_q + base;
    const float* K  = g_k + base;
    const float* E  = g_e + base;
    const float* W0 = g_wsnap + (size_t)(b * NCH + c) * HD * HD;
    float* Y = g_y + base;
    const float eta = __ldg(lr);

    __shared__ float As2[CC][68];
    __shared__ float St[8][132];
    __shared__ float Qt[8][68];

    const int tid = threadIdx.x;
    const int ty = tid >> 4;
    const int tx = tid & 15;

    // ---- Phase A: A = Q K^T  (64x64, K=128) ----
    {
        float acc[4][4];
#pragma unroll
        for (int i = 0; i < 4; i++)
#pragma unroll
            for (int j = 0; j < 4; j++) acc[i][j] = 0.f;

        for (int h0 = 0; h0 < HD; h0 += 8) {
            __syncthreads();
            if (tid < 128) {
                const int t = tid >> 1, hh = (tid & 1) << 2;
                float4 qv = *(const float4*)(Q + (size_t)t * HD + h0 + hh);
                Qt[hh + 0][t] = qv.x; Qt[hh + 1][t] = qv.y;
                Qt[hh + 2][t] = qv.z; Qt[hh + 3][t] = qv.w;
            } else {
                const int m = tid - 128;
                const int s = m >> 1, hh = (m & 1) << 2;
                float4 kv = *(const float4*)(K + (size_t)s * HD + h0 + hh);
                St[hh + 0][s] = kv.x; St[hh + 1][s] = kv.y;
                St[hh + 2][s] = kv.z; St[hh + 3][s] = kv.w;
            }
            __syncthreads();
#pragma unroll
            for (int hh = 0; hh < 8; hh++) {
                float a[4], bb[4];
#pragma unroll
                for (int i = 0; i < 4; i++) a[i]  = Qt[hh][ty * 4 + i];
#pragma unroll
                for (int j = 0; j < 4; j++) bb[j] = St[hh][tx * 4 + j];
#pragma unroll
                for (int i = 0; i < 4; i++)
#pragma unroll
                    for (int j = 0; j < 4; j++) acc[i][j] = fmaf(a[i], bb[j], acc[i][j]);
            }
        }
        __syncthreads();
#pragma unroll
        for (int i = 0; i < 4; i++)
#pragma unroll
            for (int j = 0; j < 4; j++) {
                const int t = ty * 4 + i, s = tx * 4 + j;
                As2[t][s] = (s < t) ? (-eta * acc[i][j]) : 0.f;
            }
        __syncthreads();
    }

    // ---- Phase B: Y = Q W0^T + As2 * E  (64x128) ----
    float acc[4][8];
#pragma unroll
    for (int i = 0; i < 4; i++)
#pragma unroll
        for (int j = 0; j < 8; j++) acc[i][j] = 0.f;

    for (int h0 = 0; h0 < HD; h0 += 8) {
        __syncthreads();
        if (tid < 128) {
            const int t = tid >> 1, hh = (tid & 1) << 2;
            float4 qv = *(const float4*)(Q + (size_t)t * HD + h0 + hh);
            Qt[hh + 0][t] = qv.x; Qt[hh + 1][t] = qv.y;
            Qt[hh + 2][t] = qv.z; Qt[hh + 3][t] = qv.w;
        }
        {
            const int j = tid >> 1, hh = (tid & 1) << 2;
            float4 wv = *(const float4*)(W0 + (size_t)j * HD + h0 + hh);
            St[hh + 0][j] = wv.x; St[hh + 1][j] = wv.y;
            St[hh + 2][j] = wv.z; St[hh + 3][j] = wv.w;
        }
        __syncthreads();
#pragma unroll
        for (int hh = 0; hh < 8; hh++) {
            float a[4], bb[8];
#pragma unroll
            for (int i = 0; i < 4; i++) a[i]  = Qt[hh][ty * 4 + i];
#pragma unroll
            for (int j = 0; j < 8; j++) bb[j] = St[hh][tx * 8 + j];
#pragma unroll
            for (int i = 0; i < 4; i++)
#pragma unroll
                for (int j = 0; j < 8; j++) acc[i][j] = fmaf(a[i], bb[j], acc[i][j]);
        }
    }

    for (int s0 = 0; s0 < CC; s0 += 8) {
        __syncthreads();
        {
            const int ss = tid >> 5, j4 = (tid & 31) << 2;
            float4 ev = *(const float4*)(E + (size_t)(s0 + ss) * HD + j4);
            *(float4*)&St[ss][j4] = ev;
        }
        __syncthreads();
#pragma unroll
        for (int ss = 0; ss < 8; ss++) {
            float a[4], bb[8];
#pragma unroll
            for (int i = 0; i < 4; i++) a[i]  = As2[ty * 4 + i][s0 + ss];
#pragma unroll
            for (int j = 0; j < 8; j++) bb[j] = St[ss][tx * 8 + j];
#pragma unroll
            for (int i = 0; i < 4; i++)
#pragma unroll
                for (int j = 0; j < 8; j++) acc[i][j] = fmaf(a[i], bb[j], acc[i][j]);
        }
    }

#pragma unroll
    for (int i = 0; i < 4; i++) {
        float* yr = Y + (size_t)(ty * 4 + i) * HD + tx * 8;
        *(float4*)yr       = make_float4(acc[i][0], acc[i][1], acc[i][2], acc[i][3]);
        *(float4*)(yr + 4) = make_float4(acc[i][4], acc[i][5], acc[i][6], acc[i][7]);
    }
}

// ---------------------------------------------------------------------------
// kernel_launch
// ---------------------------------------------------------------------------
extern "C" void kernel_launch(void* const* d_in, const int* in_sizes, int n_in,
                              void* d_out, int out_size)
{
    const float* x  = (const float*)d_in[0];
    const float* Wq = (const float*)d_in[1];
    const float* Wk = (const float*)d_in[2];
    const float* Wv = (const float*)d_in[3];
    const float* Wo = (const float*)d_in[4];
    const float* lr = (const float*)d_in[5];
    const float* st = (const float*)d_in[6];
    float* out = (float*)d_out;

    // q-path splits (range-safe, feedback-free operand)
    splitx_kernel<<<(BS * DD / 4) / 256, 256>>>(x);
    splitwq_kernel<<<(DD * HD) / 256, 256>>>(Wq);

    // K,V projections in fp32 (fused, double-buffered)
    dim3 gkv(1, BS / 128, 2);
    kvgemm_kernel<<<gkv, 256>>>(x, Wk, Wv);

    // Q projection on tensor cores (3-term fp16 split)
    qmma_kernel<<<BS / 128, 256>>>();

    // Gram scalars (k.k, distances 1..7)
    gram_kernel<<<(BB * SS) / 8, 256>>>();

    // Error scan (writes g_e, g_wsnap, W_final tail of d_out)
    scan_kernel<<<(BB * HD) / 2, 64>>>(lr, st, out + (size_t)BS * DD);

    // Parallel Y reconstruction per chunk (fp32 y)
    dim3 gy(NCH, BB);
    ypass_kernel<<<gy, 256>>>(lr);

    // Output projection in fp32 (y magnitude is unbounded; fp16 unsafe here)
    dim3 gout(DD / 128, BS / 128);
    outgemm_kernel<<<gout, 256>>>(Wo, out);
}

// round 12
// speedup vs baseline: 1.0512x; 1.0512x over previous
#include <cuda_runtime.h>
#include <cuda_fp16.h>

// Problem constants (fixed shapes from reference)
#define BB 4
#define SS 4096
#define DD 1024
#define HD 128
#define BS (BB*SS)   // 16384 rows
#define RR 16        // scan lookahead block size
#define NBLK (SS/RR) // 256
#define CC 64        // chunk size for y reconstruction
#define NCH (SS/CC)

// ---------------------------------------------------------------------------
// Scratch (device globals; no allocation allowed in kernel_launch)
// ---------------------------------------------------------------------------
__device__ float g_q[BB*SS*HD];
__device__ float g_k[BB*SS*HD];
__device__ float g_v[BB*SS*HD];
__device__ float g_y[BB*SS*HD];
__device__ float g_e[BB*SS*HD];
__device__ float g_gram16[BB*SS*16];      // per (b,t): G1..G15, pad; Gd = k_{t-d}.k_t
__device__ float g_wsnap[BB*NCH*HD*HD];   // W at chunk starts

// fp16-split operands: q-path ONLY (k/v feed the recurrence -> coherent split
// error is amplified ~linearly in S; q has no feedback and is safe)
__device__ __half g_xh[BS*DD], g_xl[BS*DD];
__device__ __half g_wqh[HD*DD], g_wql[HD*DD];   // Wq^T [HD][DD]

__device__ __forceinline__ float dot4(float4 a, float4 b) {
    return fmaf(a.x, b.x, fmaf(a.y, b.y, fmaf(a.z, b.z, a.w * b.w)));
}

// ---------------------------------------------------------------------------
// Split kernels: a = hi(fp16) + lo(fp16)
// ---------------------------------------------------------------------------
__global__ __launch_bounds__(256) void splitx_kernel(const float* __restrict__ x)
{
    const size_t i = (size_t)blockIdx.x * blockDim.x + threadIdx.x;  // float4 idx
    const float4 f = ((const float4*)x)[i];
    __half h0 = __float2half_rn(f.x), h1 = __float2half_rn(f.y);
    __half h2 = __float2half_rn(f.z), h3 = __float2half_rn(f.w);
    __half l0 = __float2half_rn(f.x - __half2float(h0));
    __half l1 = __float2half_rn(f.y - __half2float(h1));
    __half l2 = __float2half_rn(f.z - __half2float(h2));
    __half l3 = __float2half_rn(f.w - __half2float(h3));
    ((__half2*)g_xh)[2*i]     = __halves2half2(h0, h1);
    ((__half2*)g_xh)[2*i + 1] = __halves2half2(h2, h3);
    ((__half2*)g_xl)[2*i]     = __halves2half2(l0, l1);
    ((__half2*)g_xl)[2*i + 1] = __halves2half2(l2, l3);
}

__global__ __launch_bounds__(256) void splitwq_kernel(const float* __restrict__ Wq)
{
    const int r = blockIdx.x * blockDim.x + threadIdx.x;   // 0 .. DD*HD-1
    const int d = r >> 7, h = r & 127;
    const float f = Wq[r];
    __half hi = __float2half_rn(f);
    __half lo = __float2half_rn(f - __half2float(hi));
    g_wqh[h * DD + d] = hi;
    g_wql[h * DD + d] = lo;
}

// ---------------------------------------------------------------------------
// fp16-split tensor-core GEMM (3-term): q = x * Wq^T
// CTA tile 128x128, K-step 32, 8 warps (2x4), warp tile 64x32, m16n8k16.
// ---------------------------------------------------------------------------
__device__ __forceinline__ void mma16816(float* c, const unsigned* a, const unsigned* b)
{
    asm volatile(
        "mma.sync.aligned.m16n8k16.row.col.f32.f16.f16.f32 "
        "{%0,%1,%2,%3},{%4,%5,%6,%7},{%8,%9},{%0,%1,%2,%3};"
        : "+f"(c[0]), "+f"(c[1]), "+f"(c[2]), "+f"(c[3])
        : "r"(a[0]), "r"(a[1]), "r"(a[2]), "r"(a[3]), "r"(b[0]), "r"(b[1]));
}

__global__ __launch_bounds__(256) void qmma_kernel()
{
    __shared__ unsigned AsH[128*20], AsL[128*20], BsH[128*20], BsL[128*20];

    const int bm = blockIdx.x;
    const int N = HD, K = DD;

    const int t = threadIdx.x;
    const int lane = t & 31, wid = t >> 5;
    const int g = lane >> 2, tg = lane & 3;
    const int warpM = wid >> 2, warpN = wid & 3;

    const int lr = t >> 1, lc = t & 1;
    const __half* aPh = g_xh + (size_t)(bm * 128 + lr) * K + lc * 16;
    const __half* aPl = g_xl + (size_t)(bm * 128 + lr) * K + lc * 16;
    const __half* bPh = g_wqh + (size_t)lr * K + lc * 16;
    const __half* bPl = g_wql + (size_t)lr * K + lc * 16;
    const int sts = lr * 20 + lc * 8;

    float c[4][4][4];
#pragma unroll
    for (int mt = 0; mt < 4; mt++)
#pragma unroll
        for (int nt = 0; nt < 4; nt++)
#pragma unroll
            for (int j = 0; j < 4; j++) c[mt][nt][j] = 0.f;

    int4 ra0  = *(const int4*)aPh;       int4 ra1  = *(const int4*)(aPh + 8);
    int4 ral0 = *(const int4*)aPl;       int4 ral1 = *(const int4*)(aPl + 8);
    int4 rb0  = *(const int4*)bPh;       int4 rb1  = *(const int4*)(bPh + 8);
    int4 rbl0 = *(const int4*)bPl;       int4 rbl1 = *(const int4*)(bPl + 8);
    *(int4*)&AsH[sts] = ra0;   *(int4*)&AsH[sts + 4] = ra1;
    *(int4*)&AsL[sts] = ral0;  *(int4*)&AsL[sts + 4] = ral1;
    *(int4*)&BsH[sts] = rb0;   *(int4*)&BsH[sts + 4] = rb1;
    *(int4*)&BsL[sts] = rbl0;  *(int4*)&BsL[sts + 4] = rbl1;
    __syncthreads();

    const int KT = K / 32;
    for (int kt = 0; kt < KT; kt++) {
        if (kt + 1 < KT) {
            const int o = (kt + 1) * 32;
            ra0  = *(const int4*)(aPh + o);      ra1  = *(const int4*)(aPh + o + 8);
            ral0 = *(const int4*)(aPl + o);      ral1 = *(const int4*)(aPl + o + 8);
            rb0  = *(const int4*)(bPh + o);      rb1  = *(const int4*)(bPh + o + 8);
            rbl0 = *(const int4*)(bPl + o);      rbl1 = *(const int4*)(bPl + o + 8);
        }
#pragma unroll
        for (int s = 0; s < 2; s++) {
            unsigned aH[4][4], aL[4][4], bH[4][2], bL[4][2];
#pragma unroll
            for (int mt = 0; mt < 4; mt++) {
                const int r0 = (warpM * 64 + mt * 16 + g) * 20 + s * 8 + tg;
                aH[mt][0] = AsH[r0];       aH[mt][1] = AsH[r0 + 160];
                aH[mt][2] = AsH[r0 + 4];   aH[mt][3] = AsH[r0 + 164];
                aL[mt][0] = AsL[r0];       aL[mt][1] = AsL[r0 + 160];
                aL[mt][2] = AsL[r0 + 4];   aL[mt][3] = AsL[r0 + 164];
            }
#pragma unroll
            for (int nt = 0; nt < 4; nt++) {
                const int n0 = (warpN * 32 + nt * 8 + g) * 20 + s * 8 + tg;
                bH[nt][0] = BsH[n0];  bH[nt][1] = BsH[n0 + 4];
                bL[nt][0] = BsL[n0];  bL[nt][1] = BsL[n0 + 4];
            }
#pragma unroll
            for (int mt = 0; mt < 4; mt++)
#pragma unroll
                for (int nt = 0; nt < 4; nt++) {
                    mma16816(c[mt][nt], aH[mt], bH[nt]);
                    mma16816(c[mt][nt], aH[mt], bL[nt]);
                    mma16816(c[mt][nt], aL[mt], bH[nt]);
                }
        }
        __syncthreads();
        if (kt + 1 < KT) {
            *(int4*)&AsH[sts] = ra0;   *(int4*)&AsH[sts + 4] = ra1;
            *(int4*)&AsL[sts] = ral0;  *(int4*)&AsL[sts + 4] = ral1;
            *(int4*)&BsH[sts] = rb0;   *(int4*)&BsH[sts + 4] = rb1;
            *(int4*)&BsL[sts] = rbl0;  *(int4*)&BsL[sts + 4] = rbl1;
            __syncthreads();
        }
    }

#pragma unroll
    for (int mt = 0; mt < 4; mt++)
#pragma unroll
        for (int nt = 0; nt < 4; nt++) {
            const int row = bm * 128 + warpM * 64 + mt * 16 + g;
            const int col = warpN * 32 + nt * 8 + 2 * tg;
            *(float2*)&g_q[(size_t)row * N + col]       = make_float2(c[mt][nt][0], c[mt][nt][1]);
            *(float2*)&g_q[(size_t)(row + 8) * N + col] = make_float2(c[mt][nt][2], c[mt][nt][3]);
        }
}

// ---------------------------------------------------------------------------
// fp32 SGEMM body (R9 known-good, single-buffered): C = A[M,K]*B[K,N]
// ---------------------------------------------------------------------------
__device__ __forceinline__ void sgemm_body(
    const float* __restrict__ A, const float* __restrict__ Bm,
    float* __restrict__ C, int M, int N, int K, int bx, int by)
{
    __shared__ float As[8][128];
    __shared__ float Bs[8][132];

    const int tid = threadIdx.x;
    const int ty = tid >> 4;
    const int tx = tid & 15;
    const int a_r = tid >> 1;
    const int a_c = (tid & 1) << 2;
    const int b_r = tid >> 5;
    const int b_c = (tid & 31) << 2;

    const float* Ab = A + (size_t)by * 128 * K;
    const float* Bb = Bm + bx * 128;

    float acc[8][8];
#pragma unroll
    for (int i = 0; i < 8; i++)
#pragma unroll
        for (int j = 0; j < 8; j++) acc[i][j] = 0.f;

    for (int k0 = 0; k0 < K; k0 += 8) {
        float4 av = *(const float4*)(Ab + (size_t)a_r * K + k0 + a_c);
        float4 bv = *(const float4*)(Bb + (size_t)(k0 + b_r) * N + b_c);
        __syncthreads();
        As[a_c + 0][a_r] = av.x;
        As[a_c + 1][a_r] = av.y;
        As[a_c + 2][a_r] = av.z;
        As[a_c + 3][a_r] = av.w;
        *(float4*)&Bs[b_r][b_c] = bv;
        __syncthreads();
#pragma unroll
        for (int kk = 0; kk < 8; kk++) {
            float a[8], b[8];
#pragma unroll
            for (int i = 0; i < 8; i++) a[i] = As[kk][ty * 8 + i];
#pragma unroll
            for (int j = 0; j < 8; j++) b[j] = Bs[kk][tx * 8 + j];
#pragma unroll
            for (int i = 0; i < 8; i++)
#pragma unroll
                for (int j = 0; j < 8; j++) acc[i][j] = fmaf(a[i], b[j], acc[i][j]);
        }
    }

    float* Cb = C + (size_t)(by * 128 + ty * 8) * N + bx * 128 + tx * 8;
#pragma unroll
    for (int i = 0; i < 8; i++) {
        *(float4*)(Cb + (size_t)i * N)     = make_float4(acc[i][0], acc[i][1], acc[i][2], acc[i][3]);
        *(float4*)(Cb + (size_t)i * N + 4) = make_float4(acc[i][4], acc[i][5], acc[i][6], acc[i][7]);
    }
}

// Fused K,V projections in fp32 (recurrence-sensitive operands)
__global__ __launch_bounds__(256) void kvgemm_kernel(
    const float* __restrict__ x, const float* __restrict__ Wk,
    const float* __restrict__ Wv)
{
    const float* Bm = (blockIdx.z == 0) ? Wk : Wv;
    float* C = (blockIdx.z == 0) ? g_k : g_v;
    sgemm_body(x, Bm, C, BS, HD, DD, 0, blockIdx.y);
}

__global__ __launch_bounds__(256) void outgemm_kernel(
    const float* __restrict__ Wo, float* __restrict__ out)
{
    sgemm_body(g_y, Wo, out, BS, DD, HD, blockIdx.x, blockIdx.y);
}

// ---------------------------------------------------------------------------
// Gram kernel: one warp per (b,t): G_d[t] = k_{t-d}.k_t for d=1..15
// ---------------------------------------------------------------------------
__global__ __launch_bounds__(256) void gram_kernel()
{
    const int w = (blockIdx.x * blockDim.x + threadIdx.x) >> 5;  // b*SS + t
    const int lane = threadIdx.x & 31;
    if (w >= BB * SS) return;
    const int t = w & (SS - 1);

    float4 kc = *(const float4*)(g_k + (size_t)w * HD + lane * 4);
    float dd[15];
#pragma unroll
    for (int d2 = 1; d2 <= 15; d2++) {
        float4 kd = make_float4(0.f, 0.f, 0.f, 0.f);
        if (t >= d2) kd = *(const float4*)(g_k + (size_t)(w - d2) * HD + lane * 4);
        dd[d2 - 1] = dot4(kd, kc);
    }
#pragma unroll
    for (int s = 16; s; s >>= 1) {
#pragma unroll
        for (int j = 0; j < 15; j++) dd[j] += __shfl_xor_sync(~0u, dd[j], s);
    }
    if (lane == 0) {
        float* gp = g_gram16 + (size_t)w * 16;
        *(float4*)(gp)      = make_float4(dd[0],  dd[1],  dd[2],  dd[3]);
        *(float4*)(gp + 4)  = make_float4(dd[4],  dd[5],  dd[6],  dd[7]);
        *(float4*)(gp + 8)  = make_float4(dd[8],  dd[9],  dd[10], dd[11]);
        *(float4*)(gp + 12) = make_float4(dd[12], dd[13], dd[14], 0.f);
    }
}

// ---------------------------------------------------------------------------
// Blocked-lookahead error scan, R=16. k via 2-stage cp.async smem pipeline
// (depth-1 prefetch, wait_group 1); v depth-2 register prefetch; Gram via
// smem double buffer. One warp per (batch, W-row), 2 warps/CTA.
// ---------------------------------------------------------------------------
__device__ __forceinline__ void cp_async16(unsigned smem_addr, const void* gptr)
{
    asm volatile("cp.async.cg.shared.global [%0], [%1], 16;"
                 :: "r"(smem_addr), "l"(gptr));
}
__device__ __forceinline__ void cp_commit() {
    asm volatile("cp.async.commit_group;");
}
__device__ __forceinline__ void cp_wait1() {
    asm volatile("cp.async.wait_group 1;");
}

__global__ __launch_bounds__(64) void scan_kernel(
    const float* __restrict__ lr, const float* __restrict__ state,
    float* __restrict__ wfinal)
{
    __shared__ float  ksm[2][2][RR][HD];   // [warp][stage][row][float] = 32KB
    __shared__ float4 gwbuf[2][2][64];     // [warp][buffer][16t x 4f4] = 4KB

    const int warp = (blockIdx.x * blockDim.x + threadIdx.x) >> 5;  // 0..511
    const int wl = (threadIdx.x >> 5);
    const int lane = threadIdx.x & 31;
    const int b = warp >> 7;
    const int i = warp & 127;
    const float eta = __ldg(lr);

    const float* kp = g_k + (size_t)b * SS * HD;
    const float* vp = g_v + (size_t)b * SS * HD + i;
    const float4* gp4 = (const float4*)(g_gram16 + (size_t)b * SS * 16);
    float* ep = g_e + (size_t)b * SS * HD + i;

    float4 Wr = *(const float4*)(state + (size_t)(b * HD + i) * HD + lane * 4);

    unsigned kbase = (unsigned)__cvta_generic_to_shared(&ksm[wl][0][0][lane * 4]);
    const unsigned KSTAGE = RR * HD * 4;   // 8192 bytes

    float vc[RR], vn1[RR], vn2[RR];
    // prologue: stage0 <- block0
#pragma unroll
    for (int r = 0; r < RR; r++)
        cp_async16(kbase + r * (HD * 4), kp + (size_t)r * HD + lane * 4);
    cp_commit();
#pragma unroll
    for (int r = 0; r < RR; r++) {
        vc[r]  = vp[(size_t)r * HD];
        vn1[r] = vp[(size_t)(RR + r) * HD];
    }
    gwbuf[wl][0][lane]      = gp4[lane];
    gwbuf[wl][0][lane + 32] = gp4[lane + 32];
    __syncwarp();

    for (int blk = 0; blk < NBLK; blk++) {
        const int T = blk * RR;
        const int cur = blk & 1;

        // chunk-start snapshot (Wr == W_{T-1}; CC/RR = 4)
        if ((blk & 3) == 0) {
            const int c = blk >> 2;
            *(float4*)(g_wsnap + ((size_t)((b * NCH + c) * HD + i)) * HD + lane * 4) = Wr;
        }

        // prefetch k for blk+1 into stage cur^1
        const int T1 = ((blk + 1 < NBLK) ? (blk + 1) : (NBLK - 1)) * RR;
#pragma unroll
        for (int r = 0; r < RR; r++)
            cp_async16(kbase + (cur ^ 1) * KSTAGE + r * (HD * 4),
                       kp + (size_t)(T1 + r) * HD + lane * 4);
        cp_commit();

        // v prefetch depth 2 (registers)
        const int T2 = ((blk + 2 < NBLK) ? (blk + 2) : (NBLK - 1)) * RR;
#pragma unroll
        for (int r = 0; r < RR; r++) vn2[r] = vp[(size_t)(T2 + r) * HD];

        // gram prefetch depth 1 (registers)
        float4 ga = gp4[(size_t)T1 * 4 + lane];
        float4 gb = gp4[(size_t)T1 * 4 + 32 + lane];

        // current k stage ready once only the just-issued group is outstanding
        cp_wait1();

        // 16 dots against fixed basis (each lane reads the 16B it copied)
        float d[RR];
#pragma unroll
        for (int r = 0; r < RR; r++) {
            float4 kk4 = *(const float4*)&ksm[wl][cur][r][lane * 4];
            d[r] = dot4(kk4, Wr);
        }
        // pipelined 5-stage shuffle reduction over 16 independent values
#pragma unroll
        for (int s = 16; s; s >>= 1) {
#pragma unroll
            for (int j = 0; j < RR; j++) d[j] += __shfl_xor_sync(~0u, d[j], s);
        }

        // publish next gram block
        gwbuf[wl][cur ^ 1][lane]      = ga;
        gwbuf[wl][cur ^ 1][lane + 32] = gb;
        __syncwarp();

        // serial scalar recurrence; Gram scalars read straight from smem
        const float* gbuf = (const float*)&gwbuf[wl][cur][0];
        float e[RR], ee[RR];
#pragma unroll
        for (int r = 0; r < RR; r++) {
            float acc = d[r] - vc[r];
#pragma unroll
            for (int dd2 = r; dd2 >= 1; --dd2)
                acc = fmaf(-ee[r - dd2], gbuf[r * 16 + dd2 - 1], acc);
            e[r] = acc;
            ee[r] = eta * acc;
        }

        if (lane == 0) {
#pragma unroll
            for (int r = 0; r < RR; r++) ep[(size_t)(T + r) * HD] = e[r];
        }

        // rank-16 update of basis (re-read k slices from smem)
#pragma unroll
        for (int r = 0; r < RR; r++) {
            float4 kk4 = *(const float4*)&ksm[wl][cur][r][lane * 4];
            Wr.x = fmaf(-ee[r], kk4.x, Wr.x);
            Wr.y = fmaf(-ee[r], kk4.y, Wr.y);
            Wr.z = fmaf(-ee[r], kk4.z, Wr.z);
            Wr.w = fmaf(-ee[r], kk4.w, Wr.w);
        }

        // rotate v buffers
#pragma unroll
        for (int r = 0; r < RR; r++) { vc[r] = vn1[r]; vn1[r] = vn2[r]; }
    }

    *(float4*)(wfinal + (size_t)(b * HD + i) * HD + lane * 4) = Wr;
}

// ---------------------------------------------------------------------------
// ypass: per (chunk c, batch b) CTA reconstructs
//   Y = Q_c * W0^T - eta * tril_strict(Q_c K_c^T) * E_c   (fp32 output)
// ---------------------------------------------------------------------------
__global__ __launch_bounds__(256) void ypass_kernel(const float* __restrict__ lr)
{
    const int c = blockIdx.x, b = blockIdx.y;
    const size_t base = ((size_t)b * SS + (size_t)c * CC) * HD;
    const float* Q  = g_q + base;
    const float* K  = g_k + base;
    const float* E  = g_e + base;
    const float* W0 = g_wsnap + (size_t)(b * NCH + c) * HD * HD;
    float* Y = g_y + base;
    const float eta = __ldg(lr);

    __shared__ float As2[CC][68];
    __shared__ float St[8][132];
    __shared__ float Qt[8][68];

    const int tid = threadIdx.x;
    const int ty = tid >> 4;
    const int tx = tid & 15;

    // ---- Phase A: A = Q K^T  (64x64, K=128) ----
    {
        float acc[4][4];
#pragma unroll
        for (int i = 0; i < 4; i++)
#pragma unroll
            for (int j = 0; j < 4; j++) acc[i][j] = 0.f;

        for (int h0 = 0; h0 < HD; h0 += 8) {
            __syncthreads();
            if (tid < 128) {
                const int t = tid >> 1, hh = (tid & 1) << 2;
                float4 qv = *(const float4*)(Q + (size_t)t * HD + h0 + hh);
                Qt[hh + 0][t] = qv.x; Qt[hh + 1][t] = qv.y;
                Qt[hh + 2][t] = qv.z; Qt[hh + 3][t] = qv.w;
            } else {
                const int m = tid - 128;
                const int s = m >> 1, hh = (m & 1) << 2;
                float4 kv = *(const float4*)(K + (size_t)s * HD + h0 + hh);
                St[hh + 0][s] = kv.x; St[hh + 1][s] = kv.y;
                St[hh + 2][s] = kv.z; St[hh + 3][s] = kv.w;
            }
            __syncthreads();
#pragma unroll
            for (int hh = 0; hh < 8; hh++) {
                float a[4], bb[4];
#pragma unroll
                for (int i = 0; i < 4; i++) a[i]  = Qt[hh][ty * 4 + i];
#pragma unroll
                for (int j = 0; j < 4; j++) bb[j] = St[hh][tx * 4 + j];
#pragma unroll
                for (int i = 0; i < 4; i++)
#pragma unroll
                    for (int j = 0; j < 4; j++) acc[i][j] = fmaf(a[i], bb[j], acc[i][j]);
            }
        }
        __syncthreads();
#pragma unroll
        for (int i = 0; i < 4; i++)
#pragma unroll
            for (int j = 0; j < 4; j++) {
                const int t = ty * 4 + i, s = tx * 4 + j;
                As2[t][s] = (s < t) ? (-eta * acc[i][j]) : 0.f;
            }
        __syncthreads();
    }

    // ---- Phase B: Y = Q W0^T + As2 * E  (64x128) ----
    float acc[4][8];
#pragma unroll
    for (int i = 0; i < 4; i++)
#pragma unroll
        for (int j = 0; j < 8; j++) acc[i][j] = 0.f;

    for (int h0 = 0; h0 < HD; h0 += 8) {
        __syncthreads();
        if (tid < 128) {
            const int t = tid >> 1, hh = (tid & 1) << 2;
            float4 qv = *(const float4*)(Q + (size_t)t * HD + h0 + hh);
            Qt[hh + 0][t] = qv.x; Qt[hh + 1][t] = qv.y;
            Qt[hh + 2][t] = qv.z; Qt[hh + 3][t] = qv.w;
        }
        {
            const int j = tid >> 1, hh = (tid & 1) << 2;
            float4 wv = *(const float4*)(W0 + (size_t)j * HD + h0 + hh);
            St[hh + 0][j] = wv.x; St[hh + 1][j] = wv.y;
            St[hh + 2][j] = wv.z; St[hh + 3][j] = wv.w;
        }
        __syncthreads();
#pragma unroll
        for (int hh = 0; hh < 8; hh++) {
            float a[4], bb[8];
#pragma unroll
            for (int i = 0; i < 4; i++) a[i]  = Qt[hh][ty * 4 + i];
#pragma unroll
            for (int j = 0; j < 8; j++) bb[j] = St[hh][tx * 8 + j];
#pragma unroll
            for (int i = 0; i < 4; i++)
#pragma unroll
                for (int j = 0; j < 8; j++) acc[i][j] = fmaf(a[i], bb[j], acc[i][j]);
        }
    }

    for (int s0 = 0; s0 < CC; s0 += 8) {
        __syncthreads();
        {
            const int ss = tid >> 5, j4 = (tid & 31) << 2;
            float4 ev = *(const float4*)(E + (size_t)(s0 + ss) * HD + j4);
            *(float4*)&St[ss][j4] = ev;
        }
        __syncthreads();
#pragma unroll
        for (int ss = 0; ss < 8; ss++) {
            float a[4], bb[8];
#pragma unroll
            for (int i = 0; i < 4; i++) a[i]  = As2[ty * 4 + i][s0 + ss];
#pragma unroll
            for (int j = 0; j < 8; j++) bb[j] = St[ss][tx * 8 + j];
#pragma unroll
            for (int i = 0; i < 4; i++)
#pragma unroll
                for (int j = 0; j < 8; j++) acc[i][j] = fmaf(a[i], bb[j], acc[i][j]);
        }
    }

#pragma unroll
    for (int i = 0; i < 4; i++) {
        float* yr = Y + (size_t)(ty * 4 + i) * HD + tx * 8;
        *(float4*)yr       = make_float4(acc[i][0], acc[i][1], acc[i][2], acc[i][3]);
        *(float4*)(yr + 4) = make_float4(acc[i][4], acc[i][5], acc[i][6], acc[i][7]);
    }
}

// ---------------------------------------------------------------------------
// kernel_launch
// ---------------------------------------------------------------------------
extern "C" void kernel_launch(void* const* d_in, const int* in_sizes, int n_in,
                              void* d_out, int out_size)
{
    const float* x  = (const float*)d_in[0];
    const float* Wq = (const float*)d_in[1];
    const float* Wk = (const float*)d_in[2];
    const float* Wv = (const float*)d_in[3];
    const float* Wo = (const float*)d_in[4];
    const float* lr = (const float*)d_in[5];
    const float* st = (const float*)d_in[6];
    float* out = (float*)d_out;

    // q-path splits (range-safe, feedback-free operand)
    splitx_kernel<<<(BS * DD / 4) / 256, 256>>>(x);
    splitwq_kernel<<<(DD * HD) / 256, 256>>>(Wq);

    // K,V projections in fp32 (fused)
    dim3 gkv(1, BS / 128, 2);
    kvgemm_kernel<<<gkv, 256>>>(x, Wk, Wv);

    // Q projection on tensor cores (3-term fp16 split)
    qmma_kernel<<<BS / 128, 256>>>();

    // Gram scalars (k.k, distances 1..15)
    gram_kernel<<<(BB * SS) / 8, 256>>>();

    // Error scan (writes g_e, g_wsnap, W_final tail of d_out)
    scan_kernel<<<(BB * HD) / 2, 64>>>(lr, st, out + (size_t)BS * DD);

    // Parallel Y reconstruction per chunk (fp32 y)
    dim3 gy(NCH, BB);
    ypass_kernel<<<gy, 256>>>(lr);

    // Output projection in fp32 (y magnitude is unbounded; fp16 unsafe here)
    dim3 gout(DD / 128, BS / 128);
    outgemm_kernel<<<gout, 256>>>(Wo, out);
}